// round 2
// baseline (speedup 1.0000x reference)
#include <cuda_runtime.h>

// OcrEmbedding: out[b,t,:] = sum_{s=0..3, id!=0} table[id[b,t,s], :]
// B=32, T=512, S=4, D=256, V=50000.
// d_in[0] = subtoken_ids (int32, B*T*S), d_in[1] = table (float32, V*D).
// Output: float32, B*T*D.
//
// Layout: 32 threads per token row (one warp == one row). Each thread owns
// two float4 chunks (lane q and q+32) of the D=256 row. Ids loaded as a
// single int4 (warp-broadcast). 8 independent table LDG.128 per thread.

#define BT   (32 * 512)   // 16384 token rows
#define D4   64           // D/4 float4 per row

__global__ __launch_bounds__(256) void ocr_embed_kernel(
    const int4* __restrict__ ids,         // [BT] int4 (4 subtoken ids)
    const float4* __restrict__ table,     // [V, D4]
    float4* __restrict__ out)             // [BT, D4]
{
    int gid  = blockIdx.x * blockDim.x + threadIdx.x;  // 0 .. BT*32-1
    int row  = gid >> 5;      // token index (warp-uniform)
    int lane = gid & 31;      // chunk 'lane' and 'lane+32'

    int4 id = __ldg(&ids[row]);   // one LDG.128, broadcast within warp

    const float4* t0 = table + (size_t)id.x * D4 + lane;
    const float4* t1 = table + (size_t)id.y * D4 + lane;
    const float4* t2 = table + (size_t)id.z * D4 + lane;
    const float4* t3 = table + (size_t)id.w * D4 + lane;

    float4 z = make_float4(0.f, 0.f, 0.f, 0.f);
    float4 a0 = z, a1 = z, b0 = z, b1 = z, c0 = z, c1 = z, e0 = z, e1 = z;

    // All 8 loads are independent -> MLP=8 per thread.
    if (id.x != 0) { a0 = __ldg(t0); a1 = __ldg(t0 + 32); }
    if (id.y != 0) { b0 = __ldg(t1); b1 = __ldg(t1 + 32); }
    if (id.z != 0) { c0 = __ldg(t2); c1 = __ldg(t2 + 32); }
    if (id.w != 0) { e0 = __ldg(t3); e1 = __ldg(t3 + 32); }

    float4 s0, s1;
    s0.x = (a0.x + b0.x) + (c0.x + e0.x);
    s0.y = (a0.y + b0.y) + (c0.y + e0.y);
    s0.z = (a0.z + b0.z) + (c0.z + e0.z);
    s0.w = (a0.w + b0.w) + (c0.w + e0.w);
    s1.x = (a1.x + b1.x) + (c1.x + e1.x);
    s1.y = (a1.y + b1.y) + (c1.y + e1.y);
    s1.z = (a1.z + b1.z) + (c1.z + e1.z);
    s1.w = (a1.w + b1.w) + (c1.w + e1.w);

    float4* o = out + (size_t)row * D4 + lane;
    o[0]  = s0;
    o[32] = s1;
}

extern "C" void kernel_launch(void* const* d_in, const int* in_sizes, int n_in,
                              void* d_out, int out_size)
{
    const int4*   ids   = (const int4*)d_in[0];
    const float4* table = (const float4*)d_in[1];
    float4*       out   = (float4*)d_out;

    const int total   = BT * 32;           // 524,288 threads
    const int threads = 256;
    const int blocks  = total / threads;   // 2048

    ocr_embed_kernel<<<blocks, threads>>>(ids, table, out);
}